// round 4
// baseline (speedup 1.0000x reference)
#include <cuda_runtime.h>
#include <stdint.h>

#define N     1024
#define NM1   1023
#define STEPS 32
#define TTOT  1900.0f
#define T0    1880.0f
#define NT    256           // threads per block
#define MAXBPSM 6           // __launch_bounds__ min blocks/SM (<=42 regs)

// fp64 compile-time fold, then cast to fp32 — matches python float64 constant folding
#define C_FD ((float)(1e-16 * (910.0 * 9.81) * (910.0 * 9.81) * (910.0 * 9.81)))

// Scratch state (device globals — no allocations allowed)
__device__ float        g_Hbuf[N * N];          // ping-pong partner of d_out
__device__ float        g_D[NM1 * NM1];         // staggered diffusivity
__device__ unsigned int g_maxD[STEPS];          // per-step max(D) as ordered uint bits
__device__ volatile unsigned int g_barCount;    // software grid barrier counter

// ---------------------------------------------------------------------------
__global__ void init_kernel(const float* __restrict__ Hinit, float* __restrict__ H0) {
    int idx = blockIdx.x * blockDim.x + threadIdx.x;
    int stride = gridDim.x * blockDim.x;
    for (int i = idx; i < N * N; i += stride) H0[i] = Hinit[i];
    if (idx < STEPS) g_maxD[idx] = 0u;
    if (idx == STEPS) g_barCount = 0u;
}

// ---------------------------------------------------------------------------
// Software grid barrier. Safe because the grid is sized to be fully
// co-resident (occupancy-query-derived). Monotonic counter: each barrier,
// every block adds 1; release via threadfence before arrival.
__device__ __forceinline__ void grid_sync(unsigned int& target, unsigned int nblocks) {
    __syncthreads();
    if (threadIdx.x == 0) {
        __threadfence();                           // release prior writes
        target += nblocks;
        atomicAdd((unsigned int*)&g_barCount, 1u);
        while (g_barCount < target) { }            // volatile spin
        __threadfence();                           // acquire
    }
    __syncthreads();
}

// ---------------------------------------------------------------------------
// Persistent kernel: all 32 steps. Each block owns a fixed contiguous chunk
// of cells for both phases -> L1-resident working set across steps.
__global__ void __launch_bounds__(NT, MAXBPSM)
glacier_persist(float* __restrict__ buf0,          // = d_out
                float* __restrict__ buf1,          // = g_Hbuf
                const float* __restrict__ Ztopo,
                const float* __restrict__ Zela)
{
    const unsigned int B  = gridDim.x;
    const unsigned int MA = NM1 * NM1;
    const unsigned int MB = N * N;
    const unsigned int chunkA = (MA + B - 1) / B;
    const unsigned int chunkB = (MB + B - 1) / B;
    const unsigned int a0 = blockIdx.x * chunkA;
    const unsigned int a1 = (a0 + chunkA < MA) ? a0 + chunkA : MA;
    const unsigned int b0 = blockIdx.x * chunkB;
    const unsigned int b1 = (b0 + chunkB < MB) ? b0 + chunkB : MB;

    __shared__ unsigned int s_max;
    float t = T0;
    unsigned int bar_target = 0;

    for (int s = 0; s < STEPS; s++) {
        const float* __restrict__ Hc = (s & 1) ? buf1 : buf0;
        float*       __restrict__ Hn = (s & 1) ? buf0 : buf1;

        // ---------------- Phase A: diffusivity + max reduction ----------------
        if (threadIdx.x == 0) s_max = 0u;
        __syncthreads();

        unsigned int lmax = 0u;
        for (unsigned int i = a0 + threadIdx.x; i < a1; i += NT) {
            unsigned int r = i / NM1;
            unsigned int c = i - r * NM1;
            unsigned int i00 = r * N + c;

            float h00 = Hc[i00],     h01 = Hc[i00 + 1];
            float h10 = Hc[i00 + N], h11 = Hc[i00 + N + 1];
            float z00 = Ztopo[i00]     + h00, z01 = Ztopo[i00 + 1]     + h01;
            float z10 = Ztopo[i00 + N] + h10, z11 = Ztopo[i00 + N + 1] + h11;

            float havg = 0.25f * (h00 + h11 + h01 + h10);
            float sx = 0.5f * ((z01 - z00) / 100.0f + (z11 - z10) / 100.0f);
            float sy = 0.5f * ((z10 - z00) / 100.0f + (z11 - z01) / 100.0f);
            float sn = sqrtf(sx * sx + sy * sy + 1e-20f);
            float h2 = havg * havg;
            float h5 = h2 * h2 * havg;
            float d  = C_FD * h5 * (sn * sn) + 1e-20f;
            g_D[i] = d;
            unsigned int db = __float_as_uint(d);   // d > 0 -> bits order as uint
            if (db > lmax) lmax = db;
        }
        unsigned int wmax = __reduce_max_sync(0xffffffffu, lmax);
        if ((threadIdx.x & 31) == 0) atomicMax(&s_max, wmax);
        __syncthreads();
        if (threadIdx.x == 0) atomicMax(&g_maxD[s], s_max);

        grid_sync(bar_target, B);

        // ---------------- Phase B: H update ----------------
        float maxD = __uint_as_float(g_maxD[s]);
        float dt = fminf(10000.0f / (2.7f * maxD), 1.0f);
        if (!(t < TTOT)) dt = 0.0f;

        for (unsigned int i = b0 + threadIdx.x; i < b1; i += NT) {
            unsigned int r = i >> 10;
            unsigned int c = i & (N - 1);
            float h = Hc[i];
            float hn;
            if (r > 0u && r < N - 1 && c > 0u && c < N - 1) {
                float Dul = g_D[(r - 1) * NM1 + (c - 1)];
                float Dur = g_D[(r - 1) * NM1 + c];
                float Dll = g_D[r * NM1 + (c - 1)];
                float Dlr = g_D[r * NM1 + c];

                float zc = Ztopo[i] + h;
                float zl = Ztopo[i - 1] + Hc[i - 1];
                float zr = Ztopo[i + 1] + Hc[i + 1];
                float zu = Ztopo[i - N] + Hc[i - N];
                float zd = Ztopo[i + N] + Hc[i + N];

                float qxL = -(0.5f * (Dul + Dll)) * (zc - zl) / 100.0f;
                float qxR = -(0.5f * (Dur + Dlr)) * (zr - zc) / 100.0f;
                float qyU = -(0.5f * (Dul + Dur)) * (zc - zu) / 100.0f;
                float qyD = -(0.5f * (Dll + Dlr)) * (zd - zc) / 100.0f;

                float dHdt = -((qxR - qxL) / 100.0f + (qyD - qyU) / 100.0f);
                float b = fminf(1e-3f * (zc - Zela[i]), 0.3f);
                hn = fmaxf(h + dt * (dHdt + b), 0.0f);
            } else {
                hn = fmaxf(h, 0.0f);
            }
            Hn[i] = hn;
        }
        t += dt;

        grid_sync(bar_target, B);   // writes visible before next step's phase A
    }
    // STEPS even -> final H lands in buf0 == d_out
}

// ---------------------------------------------------------------------------
extern "C" void kernel_launch(void* const* d_in, const int* in_sizes, int n_in,
                              void* d_out, int out_size) {
    const float* Zela  = (const float*)d_in[0];   // Z_ELA
    const float* Ztopo = (const float*)d_in[1];   // Z_topo
    const float* Hinit = (const float*)d_in[2];   // H_initial
    float* out = (float*)d_out;

    float* hbuf = nullptr;
    cudaGetSymbolAddress((void**)&hbuf, g_Hbuf);

    // Grid sized for guaranteed full co-residency (software barrier safety)
    int dev = 0, nsm = 0, bpsm = 0;
    cudaGetDevice(&dev);
    cudaDeviceGetAttribute(&nsm, cudaDevAttrMultiProcessorCount, dev);
    cudaOccupancyMaxActiveBlocksPerMultiprocessor(&bpsm, glacier_persist, NT, 0);
    if (bpsm > MAXBPSM) bpsm = MAXBPSM;
    if (bpsm < 1) bpsm = 1;
    int B = nsm * bpsm;
    if (B < 1) B = 1;

    init_kernel<<<256, 256>>>(Hinit, out);
    glacier_persist<<<B, NT>>>(out, hbuf, Ztopo, Zela);
}

// round 5
// speedup vs baseline: 1.1171x; 1.1171x over previous
#include <cuda_runtime.h>
#include <stdint.h>

#define N     1024
#define NM1   1023
#define STEPS 32
#define TTOT  1900.0f
#define T0    1880.0f
#define NT    256           // threads per block
#define MAXBPSM 6
#define MAXB  1024          // max resident blocks supported by flag array

// fp64 compile-time fold, then cast to fp32 — matches python float64 constant folding
#define C_FD ((float)(1e-16 * (910.0 * 9.81) * (910.0 * 9.81) * (910.0 * 9.81)))

// Scratch state (device globals — no allocations allowed)
__device__ float        g_Hbuf[N * N];
__device__ float        g_D[NM1 * NM1];
__device__ unsigned int g_maxD[STEPS];
// Barrier state: per-block arrival flags padded to 128B lines + one release word
__device__ volatile unsigned int g_arrive[MAXB * 32];
__device__ volatile unsigned int g_release;

// ---------------------------------------------------------------------------
__global__ void init_kernel(const float* __restrict__ Hinit, float* __restrict__ H0) {
    int idx = blockIdx.x * blockDim.x + threadIdx.x;
    int stride = gridDim.x * blockDim.x;
    for (int i = idx; i < N * N; i += stride) H0[i] = Hinit[i];
    for (int i = idx; i < MAXB * 32; i += stride) g_arrive[i] = 0u;
    if (idx < STEPS) g_maxD[idx] = 0u;
    if (idx == STEPS) g_release = 0u;
}

// ---------------------------------------------------------------------------
// Decentralized grid barrier: per-block padded arrival flags (parallel stores,
// no atomic serialization), block 0 scans + publishes a single release word,
// spinners back off with __nanosleep. Generation-counted; reset each replay
// by init_kernel. Safe: grid is occupancy-sized for full co-residency.
__device__ __forceinline__ void grid_sync(unsigned int gen, unsigned int B) {
    __syncthreads();
    if (blockIdx.x == 0) {
        for (unsigned int b = 1 + threadIdx.x; b < B; b += NT) {
            while (g_arrive[b * 32] < gen) { }
        }
        __syncthreads();
        if (threadIdx.x == 0) {
            __threadfence();
            g_release = gen;
        }
        __syncthreads();
        __threadfence();
    } else {
        if (threadIdx.x == 0) {
            __threadfence();                  // release prior writes
            g_arrive[blockIdx.x * 32] = gen;
            while (g_release < gen) __nanosleep(40);
            __threadfence();                  // acquire
        }
        __syncthreads();
    }
}

// ---------------------------------------------------------------------------
__global__ void __launch_bounds__(NT, MAXBPSM)
glacier_persist(float* __restrict__ buf0,          // = d_out
                float* __restrict__ buf1,          // = g_Hbuf
                const float* __restrict__ Ztopo,
                const float* __restrict__ Zela)
{
    const unsigned int B  = gridDim.x;
    const unsigned int MA = NM1 * NM1;
    const unsigned int MB = N * N;
    const unsigned int chunkA = (MA + B - 1) / B;
    const unsigned int chunkB = (MB + B - 1) / B;
    const unsigned int a0 = blockIdx.x * chunkA;
    const unsigned int a1 = (a0 + chunkA < MA) ? a0 + chunkA : MA;
    const unsigned int b0 = blockIdx.x * chunkB;
    const unsigned int b1 = (b0 + chunkB < MB) ? b0 + chunkB : MB;

    __shared__ unsigned int s_max;
    float t = T0;
    unsigned int gen = 0;

    for (int s = 0; s < STEPS; s++) {
        const float* __restrict__ Hc = (s & 1) ? buf1 : buf0;
        float*       __restrict__ Hn = (s & 1) ? buf0 : buf1;

        // ---------------- Phase A: diffusivity + max reduction ----------------
        if (threadIdx.x == 0) s_max = 0u;
        __syncthreads();

        unsigned int lmax = 0u;
        for (unsigned int i = a0 + threadIdx.x; i < a1; i += NT) {
            unsigned int r = i / NM1;
            unsigned int c = i - r * NM1;
            unsigned int i00 = r * N + c;

            float h00 = Hc[i00],     h01 = Hc[i00 + 1];
            float h10 = Hc[i00 + N], h11 = Hc[i00 + N + 1];
            float z00 = Ztopo[i00]     + h00, z01 = Ztopo[i00 + 1]     + h01;
            float z10 = Ztopo[i00 + N] + h10, z11 = Ztopo[i00 + N + 1] + h11;

            float havg = 0.25f * (h00 + h11 + h01 + h10);
            float sx = 0.5f * ((z01 - z00) / 100.0f + (z11 - z10) / 100.0f);
            float sy = 0.5f * ((z10 - z00) / 100.0f + (z11 - z01) / 100.0f);
            float sn = sqrtf(sx * sx + sy * sy + 1e-20f);
            float h2 = havg * havg;
            float h5 = h2 * h2 * havg;
            float d  = C_FD * h5 * (sn * sn) + 1e-20f;
            g_D[i] = d;
            unsigned int db = __float_as_uint(d);
            if (db > lmax) lmax = db;
        }
        unsigned int wmax = __reduce_max_sync(0xffffffffu, lmax);
        if ((threadIdx.x & 31) == 0) atomicMax(&s_max, wmax);
        __syncthreads();
        if (threadIdx.x == 0) atomicMax(&g_maxD[s], s_max);

        grid_sync(++gen, B);

        // ---------------- Phase B: H update ----------------
        float maxD = __uint_as_float(g_maxD[s]);
        float dt = fminf(10000.0f / (2.7f * maxD), 1.0f);
        if (!(t < TTOT)) dt = 0.0f;

        for (unsigned int i = b0 + threadIdx.x; i < b1; i += NT) {
            unsigned int r = i >> 10;
            unsigned int c = i & (N - 1);
            float h = Hc[i];
            float hn;
            if (r > 0u && r < N - 1 && c > 0u && c < N - 1) {
                float Dul = g_D[(r - 1) * NM1 + (c - 1)];
                float Dur = g_D[(r - 1) * NM1 + c];
                float Dll = g_D[r * NM1 + (c - 1)];
                float Dlr = g_D[r * NM1 + c];

                float zc = Ztopo[i] + h;
                float zl = Ztopo[i - 1] + Hc[i - 1];
                float zr = Ztopo[i + 1] + Hc[i + 1];
                float zu = Ztopo[i - N] + Hc[i - N];
                float zd = Ztopo[i + N] + Hc[i + N];

                float qxL = -(0.5f * (Dul + Dll)) * (zc - zl) / 100.0f;
                float qxR = -(0.5f * (Dur + Dlr)) * (zr - zc) / 100.0f;
                float qyU = -(0.5f * (Dul + Dur)) * (zc - zu) / 100.0f;
                float qyD = -(0.5f * (Dll + Dlr)) * (zd - zc) / 100.0f;

                float dHdt = -((qxR - qxL) / 100.0f + (qyD - qyU) / 100.0f);
                float b = fminf(1e-3f * (zc - Zela[i]), 0.3f);
                hn = fmaxf(h + dt * (dHdt + b), 0.0f);
            } else {
                hn = fmaxf(h, 0.0f);
            }
            Hn[i] = hn;
        }
        t += dt;

        grid_sync(++gen, B);
    }
    // STEPS even -> final H lands in buf0 == d_out
}

// ---------------------------------------------------------------------------
extern "C" void kernel_launch(void* const* d_in, const int* in_sizes, int n_in,
                              void* d_out, int out_size) {
    const float* Zela  = (const float*)d_in[0];
    const float* Ztopo = (const float*)d_in[1];
    const float* Hinit = (const float*)d_in[2];
    float* out = (float*)d_out;

    float* hbuf = nullptr;
    cudaGetSymbolAddress((void**)&hbuf, g_Hbuf);

    int dev = 0, nsm = 0, bpsm = 0;
    cudaGetDevice(&dev);
    cudaDeviceGetAttribute(&nsm, cudaDevAttrMultiProcessorCount, dev);
    cudaOccupancyMaxActiveBlocksPerMultiprocessor(&bpsm, glacier_persist, NT, 0);
    if (bpsm > MAXBPSM) bpsm = MAXBPSM;
    if (bpsm < 1) bpsm = 1;
    int B = nsm * bpsm;
    if (B > MAXB) B = MAXB;
    if (B < 1) B = 1;

    init_kernel<<<256, 256>>>(Hinit, out);
    glacier_persist<<<B, NT>>>(out, hbuf, Ztopo, Zela);
}

// round 6
// speedup vs baseline: 2.4705x; 2.2116x over previous
#include <cuda_runtime.h>
#include <stdint.h>

#define N      1024
#define STEPS  32
#define TTOT   1900.0f
#define T0     1880.0f
#define NT     256            // threads per block
#define NB     512            // blocks (2 rows each) — co-resident: 4/SM x 148 = 592 >= 512
#define RPB    2              // rows per block

// fp64 compile-time fold, then cast to fp32
#define C_FD ((float)(1e-16 * (910.0 * 9.81) * (910.0 * 9.81) * (910.0 * 9.81)))

// Scratch (device globals — no allocations allowed)
__device__ float        g_Hbuf[N * N];      // ping-pong partner of d_out
__device__ float        g_D[N * N];         // D, padded to stride N (rows 0..1022 used)
__device__ unsigned int g_maxD[STEPS];
__device__ unsigned int g_count;            // barrier arrival counter (monotonic)
__device__ volatile unsigned int g_release; // barrier release generation

// ---------------------------------------------------------------------------
__global__ void init_kernel(const float* __restrict__ Hinit, float* __restrict__ H0) {
    int idx = blockIdx.x * blockDim.x + threadIdx.x;
    int stride = gridDim.x * blockDim.x;
    const float4* src = (const float4*)Hinit;
    float4* dst = (float4*)H0;
    for (int i = idx; i < N * N / 4; i += stride) dst[i] = src[i];
    if (idx < STEPS) g_maxD[idx] = 0u;
    if (idx == STEPS) { g_count = 0u; g_release = 0u; }
}

// ---------------------------------------------------------------------------
// Grid barrier: one atomicAdd per block (parallel-friendly single-address RED),
// LAST arriver publishes release; spinners nanosleep-poll one line.
// Generation-counted, reset by init_kernel each replay. Grid is co-resident.
__device__ __forceinline__ void grid_sync(unsigned int gen) {
    __syncthreads();
    if (threadIdx.x == 0) {
        __threadfence();
        unsigned int prev = atomicAdd(&g_count, 1u);
        if (prev == gen * NB - 1u) {
            __threadfence();
            g_release = gen;               // last arriver releases
        } else {
            while (g_release < gen) __nanosleep(100);
        }
        __threadfence();
    }
    __syncthreads();
}

__device__ __forceinline__ float4 ld4(const float* p) {
    return *reinterpret_cast<const float4*>(p);
}

// ---------------------------------------------------------------------------
__global__ void __launch_bounds__(NT, 4)
glacier_persist(float* __restrict__ buf0,          // = d_out
                float* __restrict__ buf1,          // = g_Hbuf
                const float* __restrict__ Zt,      // Z_topo
                const float* __restrict__ Zela)
{
    const int tid = threadIdx.x;
    const int r0  = blockIdx.x * RPB;
    const int c0  = 4 * tid;

    __shared__ unsigned int s_max;
    float t = T0;
    unsigned int gen = 0;

    for (int s = 0; s < STEPS; s++) {
        // -------- early exit: dt == 0 for all remaining steps (identity) ------
        if (!(t < TTOT)) {
            if (s & 1) {  // result lives in buf1 -> move own rows to buf0
                #pragma unroll
                for (int rr = 0; rr < RPB; rr++) {
                    int r = r0 + rr;
                    *(float4*)&buf0[r * N + c0] = ld4(&buf1[r * N + c0]);
                }
            }
            return;
        }

        const float* Hc = (s & 1) ? buf1 : buf0;
        float*       Hn = (s & 1) ? buf0 : buf1;

        // ---------------- Phase A: diffusivity + max ----------------
        if (tid == 0) s_max = 0u;
        __syncthreads();

        unsigned int lmax = 0u;
        #pragma unroll
        for (int rr = 0; rr < RPB; rr++) {
            int r = r0 + rr;
            if (r <= N - 2) {
                float4 hA = ld4(&Hc[r * N + c0]);
                float4 hB = ld4(&Hc[(r + 1) * N + c0]);
                float4 zA = ld4(&Zt[r * N + c0]);
                float4 zB = ld4(&Zt[(r + 1) * N + c0]);
                float hA4 = 0.f, hB4 = 0.f, zA4 = 0.f, zB4 = 0.f;
                if (tid < NT - 1) {
                    hA4 = Hc[r * N + c0 + 4];
                    hB4 = Hc[(r + 1) * N + c0 + 4];
                    zA4 = Zt[r * N + c0 + 4];
                    zB4 = Zt[(r + 1) * N + c0 + 4];
                }
                float ha[5] = {hA.x, hA.y, hA.z, hA.w, hA4};
                float hb[5] = {hB.x, hB.y, hB.z, hB.w, hB4};
                float za[5] = {zA.x, zA.y, zA.z, zA.w, zA4};
                float zb[5] = {zB.x, zB.y, zB.z, zB.w, zB4};
                float dv[4];
                #pragma unroll
                for (int j = 0; j < 4; j++) {
                    float h00 = ha[j], h01 = ha[j + 1];
                    float h10 = hb[j], h11 = hb[j + 1];
                    float z00 = za[j] + h00, z01 = za[j + 1] + h01;
                    float z10 = zb[j] + h10, z11 = zb[j + 1] + h11;
                    float havg = 0.25f * (h00 + h11 + h01 + h10);
                    float sx = 0.5f * ((z01 - z00) / 100.0f + (z11 - z10) / 100.0f);
                    float sy = 0.5f * ((z10 - z00) / 100.0f + (z11 - z01) / 100.0f);
                    float sn2 = sx * sx + sy * sy + 1e-20f;
                    float h2 = havg * havg;
                    float h5 = h2 * h2 * havg;
                    dv[j] = C_FD * h5 * sn2 + 1e-20f;
                }
                if (tid == NT - 1) dv[3] = 0.0f;   // col 1023: padding, not a D cell
                #pragma unroll
                for (int j = 0; j < 4; j++) {
                    unsigned int db = __float_as_uint(dv[j]);  // d >= 0 -> uint-ordered
                    if (db > lmax) lmax = db;
                }
                *(float4*)&g_D[r * N + c0] = make_float4(dv[0], dv[1], dv[2], dv[3]);
            }
        }
        unsigned int wmax = __reduce_max_sync(0xffffffffu, lmax);
        if ((tid & 31) == 0) atomicMax(&s_max, wmax);
        __syncthreads();
        if (tid == 0) atomicMax(&g_maxD[s], s_max);

        grid_sync(++gen);

        // ---------------- Phase B: H update ----------------
        float maxD = __uint_as_float(g_maxD[s]);
        float dt = fminf(10000.0f / (2.7f * maxD), 1.0f);   // t < TTOT guaranteed here

        #pragma unroll
        for (int rr = 0; rr < RPB; rr++) {
            int r = r0 + rr;
            if (r == 0 || r == N - 1) {
                float4 v = ld4(&Hc[r * N + c0]);
                *(float4*)&Hn[r * N + c0] =
                    make_float4(fmaxf(v.x, 0.f), fmaxf(v.y, 0.f),
                                fmaxf(v.z, 0.f), fmaxf(v.w, 0.f));
            } else {
                float4 hM = ld4(&Hc[(r - 1) * N + c0]);
                float4 hC = ld4(&Hc[r * N + c0]);
                float4 hP = ld4(&Hc[(r + 1) * N + c0]);
                float4 zM = ld4(&Zt[(r - 1) * N + c0]);
                float4 zC = ld4(&Zt[r * N + c0]);
                float4 zP = ld4(&Zt[(r + 1) * N + c0]);
                float4 dM = ld4(&g_D[(r - 1) * N + c0]);
                float4 dC = ld4(&g_D[r * N + c0]);
                float4 el = ld4(&Zela[r * N + c0]);

                float hCl = 0.f, zCl = 0.f, dMl = 0.f, dCl = 0.f;
                float hCr = 0.f, zCr = 0.f;
                if (tid > 0) {
                    hCl = Hc[r * N + c0 - 1];
                    zCl = Zt[r * N + c0 - 1];
                    dMl = g_D[(r - 1) * N + c0 - 1];
                    dCl = g_D[r * N + c0 - 1];
                }
                if (tid < NT - 1) {
                    hCr = Hc[r * N + c0 + 4];
                    zCr = Zt[r * N + c0 + 4];
                }
                // Zs at cols c0-1 .. c0+4
                float zs[6] = { zCl + hCl, zC.x + hC.x, zC.y + hC.y,
                                zC.z + hC.z, zC.w + hC.w, zCr + hCr };
                float hcv[4] = { hC.x, hC.y, hC.z, hC.w };
                float zuv[4] = { zM.x + hM.x, zM.y + hM.y, zM.z + hM.z, zM.w + hM.w };
                float zdv[4] = { zP.x + hP.x, zP.y + hP.y, zP.z + hP.z, zP.w + hP.w };
                float dm[5]  = { dMl, dM.x, dM.y, dM.z, dM.w };   // D[r-1], cols c0-1..c0+3
                float dcv[5] = { dCl, dC.x, dC.y, dC.z, dC.w };   // D[r],   cols c0-1..c0+3
                float elv[4] = { el.x, el.y, el.z, el.w };
                float out[4];
                #pragma unroll
                for (int j = 0; j < 4; j++) {
                    int c = c0 + j;
                    float h = hcv[j];
                    if (c == 0 || c == N - 1) {
                        out[j] = fmaxf(h, 0.0f);
                    } else {
                        float zc = zs[j + 1], zl = zs[j], zr = zs[j + 2];
                        float zu = zuv[j], zd = zdv[j];
                        float Dul = dm[j], Dur = dm[j + 1];
                        float Dll = dcv[j], Dlr = dcv[j + 1];

                        float qxL = -(0.5f * (Dul + Dll)) * (zc - zl) / 100.0f;
                        float qxR = -(0.5f * (Dur + Dlr)) * (zr - zc) / 100.0f;
                        float qyU = -(0.5f * (Dul + Dur)) * (zc - zu) / 100.0f;
                        float qyD = -(0.5f * (Dll + Dlr)) * (zd - zc) / 100.0f;

                        float dHdt = -((qxR - qxL) / 100.0f + (qyD - qyU) / 100.0f);
                        float b = fminf(1e-3f * (zc - elv[j]), 0.3f);
                        out[j] = fmaxf(h + dt * (dHdt + b), 0.0f);
                    }
                }
                *(float4*)&Hn[r * N + c0] = make_float4(out[0], out[1], out[2], out[3]);
            }
        }
        t += dt;

        grid_sync(++gen);
    }
    // all 32 steps done: STEPS even -> result in buf0 == d_out
}

// ---------------------------------------------------------------------------
extern "C" void kernel_launch(void* const* d_in, const int* in_sizes, int n_in,
                              void* d_out, int out_size) {
    const float* Zela  = (const float*)d_in[0];
    const float* Ztopo = (const float*)d_in[1];
    const float* Hinit = (const float*)d_in[2];
    float* out = (float*)d_out;

    float* hbuf = nullptr;
    cudaGetSymbolAddress((void**)&hbuf, g_Hbuf);

    init_kernel<<<NB, NT>>>(Hinit, out);
    glacier_persist<<<NB, NT>>>(out, hbuf, Ztopo, Zela);
}